// round 2
// baseline (speedup 1.0000x reference)
#include <cuda_runtime.h>

#define N_NODES 100000
#define N_EDGES 600000
#define IN_CH 128
#define HID 128

// Scratch for per-node precompute: u = x @ W1[0:128,:], v = x @ W1[128:256,:]
__device__ float g_u[(size_t)N_NODES * HID];
__device__ float g_v[(size_t)N_NODES * HID];

// ---------------- f32x2 packed-math helpers (Blackwell FFMA2) ----------------
__device__ __forceinline__ unsigned long long pack2(float lo, float hi) {
    unsigned long long r;
    asm("mov.b64 %0, {%1, %2};" : "=l"(r) : "f"(lo), "f"(hi));
    return r;
}
__device__ __forceinline__ void unpack2(unsigned long long p, float& lo, float& hi) {
    asm("mov.b64 {%0, %1}, %2;" : "=f"(lo), "=f"(hi) : "l"(p));
}
__device__ __forceinline__ unsigned long long ffma2(unsigned long long a,
                                                    unsigned long long b,
                                                    unsigned long long c) {
    unsigned long long d;
    asm("fma.rn.f32x2 %0, %1, %2, %3;" : "=l"(d) : "l"(a), "l"(b), "l"(c));
    return d;
}

__device__ __forceinline__ float eluf(float v) {
    return v > 0.0f ? v : (__expf(v) - 1.0f);
}

// ---------------- shared GEMM tile body ----------------
// C[64][128] (+)= As[64][K=128] @ B[128][128]
// As in smem with row stride 132. Ws = smem staging 32x128.
// Thread (r = tid>>4, c = tid&15) owns rows m0=r*4..+3, cols n0=c*8..+7,
// accumulators packed as 4x4 f32x2 (pairs over N).
__device__ __forceinline__ void gemm_tile(const float* __restrict__ As,
                                          const float* __restrict__ Bglob,
                                          float* Ws, int tid, int m0, int n0,
                                          unsigned long long acc[4][4]) {
#pragma unroll 1
    for (int kt = 0; kt < 128; kt += 32) {
        __syncthreads();
#pragma unroll
        for (int it = 0; it < 4; ++it) {
            int f4 = tid + 256 * it;           // 0..1023 float4 slots
            int krow = f4 >> 5;
            int col4 = (f4 & 31) << 2;
            *(float4*)(Ws + krow * 128 + col4) =
                *(const float4*)(Bglob + (size_t)(kt + krow) * 128 + col4);
        }
        __syncthreads();
#pragma unroll
        for (int kk = 0; kk < 32; ++kk) {
            const ulonglong2* bp = (const ulonglong2*)(Ws + kk * 128 + n0);
            ulonglong2 b01 = bp[0];
            ulonglong2 b23 = bp[1];
#pragma unroll
            for (int i = 0; i < 4; ++i) {
                float a = As[(m0 + i) * 132 + kt + kk];
                unsigned long long ap = pack2(a, a);
                acc[i][0] = ffma2(ap, b01.x, acc[i][0]);
                acc[i][1] = ffma2(ap, b01.y, acc[i][1]);
                acc[i][2] = ffma2(ap, b23.x, acc[i][2]);
                acc[i][3] = ffma2(ap, b23.y, acc[i][3]);
            }
        }
    }
}

// ---------------- kernel 1: per-node precompute u, v ----------------
__global__ __launch_bounds__(256) void node_precompute(
    const float* __restrict__ x, const float* __restrict__ W1) {
    extern __shared__ float sm[];
    float* As = sm;              // 64 x 132
    float* Ws = sm + 64 * 132;   // 32 x 128

    int tid = threadIdx.x;
    int nbase = blockIdx.x * 64;

    // Load x tile (zero-fill tail rows)
#pragma unroll
    for (int it = 0; it < 8; ++it) {
        int f4 = tid + 256 * it;         // 0..2047
        int row = f4 >> 5;
        int col4 = (f4 & 31) << 2;
        int node = nbase + row;
        float4 val = make_float4(0.f, 0.f, 0.f, 0.f);
        if (node < N_NODES)
            val = *(const float4*)(x + (size_t)node * IN_CH + col4);
        *(float4*)(As + row * 132 + col4) = val;
    }

    int r = tid >> 4, c = tid & 15;
    int m0 = r * 4, n0 = c * 8;

#pragma unroll 1
    for (int half = 0; half < 2; ++half) {
        const float* B = W1 + (size_t)half * 128 * 128;
        unsigned long long acc[4][4];
#pragma unroll
        for (int i = 0; i < 4; ++i)
#pragma unroll
            for (int j = 0; j < 4; ++j) acc[i][j] = 0ULL;

        gemm_tile(As, B, Ws, tid, m0, n0, acc);

        float* dst = half ? g_v : g_u;
#pragma unroll
        for (int i = 0; i < 4; ++i) {
            int node = nbase + m0 + i;
            if (node < N_NODES) {
                float o[8];
                unpack2(acc[i][0], o[0], o[1]);
                unpack2(acc[i][1], o[2], o[3]);
                unpack2(acc[i][2], o[4], o[5]);
                unpack2(acc[i][3], o[6], o[7]);
                float4* dp = (float4*)(dst + (size_t)node * HID + n0);
                dp[0] = make_float4(o[0], o[1], o[2], o[3]);
                dp[1] = make_float4(o[4], o[5], o[6], o[7]);
            }
        }
        // Ws reuse across halves is protected by the __syncthreads at the
        // top of gemm_tile's kt loop.
    }
}

// ---------------- kernel 2: per-edge fused MLP ----------------
__global__ __launch_bounds__(256) void edge_mlp(
    const int* __restrict__ ei,          // int32 on device (harness downcasts int64)
    const float* __restrict__ b1,
    const float* __restrict__ W2, const float* __restrict__ b2,
    const float* __restrict__ W3, const float* __restrict__ b3,
    float* __restrict__ out) {
    extern __shared__ float sm[];
    float* Hs = sm;              // 64 x 132 : elu(u[src]+v[tgt]+b1)
    float* Ws = sm + 64 * 132;   // 32 x 128

    int tid = threadIdx.x;
    int ebase = blockIdx.x * 64;

    // ---- gather + layer-1 epilogue (add + bias + elu) ----
    {
        int m = tid >> 2;        // 0..63  edge within tile
        int q = tid & 3;         // quarter of the 128-wide row
        int src = ei[ebase + m];
        int tgt = ei[N_EDGES + ebase + m];
        const float* up = g_u + (size_t)src * HID;
        const float* vp = g_v + (size_t)tgt * HID;
#pragma unroll
        for (int i = 0; i < 8; ++i) {
            int col = i * 16 + q * 4;    // 4 threads per edge, contiguous per iter
            float4 a = *(const float4*)(up + col);
            float4 b = *(const float4*)(vp + col);
            float4 bi = *(const float4*)(b1 + col);
            float4 h;
            h.x = eluf(a.x + b.x + bi.x);
            h.y = eluf(a.y + b.y + bi.y);
            h.z = eluf(a.z + b.z + bi.z);
            h.w = eluf(a.w + b.w + bi.w);
            *(float4*)(Hs + m * 132 + col) = h;
        }
    }

    // ---- layer 2: Hs @ W2 + b2 ----
    int r = tid >> 4, c = tid & 15;
    int m0 = r * 4, n0 = c * 8;

    unsigned long long acc[4][4];
    {
        ulonglong2 t0 = *(const ulonglong2*)(b2 + n0);
        ulonglong2 t1 = *(const ulonglong2*)(b2 + n0 + 4);
#pragma unroll
        for (int i = 0; i < 4; ++i) {
            acc[i][0] = t0.x; acc[i][1] = t0.y;
            acc[i][2] = t1.x; acc[i][3] = t1.y;
        }
    }

    gemm_tile(Hs, W2, Ws, tid, m0, n0, acc);   // first sync also covers Hs writes

    // ---- layer 3: elu + dot with W3 + reduce ----
    float4 w3a = *(const float4*)(W3 + n0);
    float4 w3b = *(const float4*)(W3 + n0 + 4);
    float bias3 = b3[0];

    float part[4];
#pragma unroll
    for (int i = 0; i < 4; ++i) {
        float o[8];
        unpack2(acc[i][0], o[0], o[1]);
        unpack2(acc[i][1], o[2], o[3]);
        unpack2(acc[i][2], o[4], o[5]);
        unpack2(acc[i][3], o[6], o[7]);
        float p;
        p  = eluf(o[0]) * w3a.x;
        p += eluf(o[1]) * w3a.y;
        p += eluf(o[2]) * w3a.z;
        p += eluf(o[3]) * w3a.w;
        p += eluf(o[4]) * w3b.x;
        p += eluf(o[5]) * w3b.y;
        p += eluf(o[6]) * w3b.z;
        p += eluf(o[7]) * w3b.w;
        part[i] = p;
    }

    // reduce across the 16 column-threads (one 16-lane shuffle segment = one r)
#pragma unroll
    for (int i = 0; i < 4; ++i) {
#pragma unroll
        for (int off = 8; off > 0; off >>= 1)
            part[i] += __shfl_xor_sync(0xffffffffu, part[i], off, 16);
    }

    if (c == 0) {
#pragma unroll
        for (int i = 0; i < 4; ++i)
            out[ebase + m0 + i] = part[i] + bias3;
    }
}

// ---------------- launch ----------------
extern "C" void kernel_launch(void* const* d_in, const int* in_sizes, int n_in,
                              void* d_out, int out_size) {
    const float* x  = (const float*)d_in[0];
    const int*   ei = (const int*)d_in[1];     // int64 in reference -> int32 on device
    const float* W1 = (const float*)d_in[2];
    const float* b1 = (const float*)d_in[3];
    const float* W2 = (const float*)d_in[4];
    const float* b2 = (const float*)d_in[5];
    const float* W3 = (const float*)d_in[6];
    const float* b3 = (const float*)d_in[7];
    float* out = (float*)d_out;

    const int SMEM_BYTES = (64 * 132 + 32 * 128) * (int)sizeof(float);  // 50176

    cudaFuncSetAttribute(node_precompute,
                         cudaFuncAttributeMaxDynamicSharedMemorySize, SMEM_BYTES);
    cudaFuncSetAttribute(edge_mlp,
                         cudaFuncAttributeMaxDynamicSharedMemorySize, SMEM_BYTES);

    node_precompute<<<(N_NODES + 63) / 64, 256, SMEM_BYTES>>>(x, W1);
    edge_mlp<<<N_EDGES / 64, 256, SMEM_BYTES>>>(ei, b1, W2, b2, W3, b3, out);
}

// round 3
// speedup vs baseline: 1.2871x; 1.2871x over previous
#include <cuda_runtime.h>

#define N_NODES 100000
#define N_EDGES 600000
#define HID 128
#define AS_STRIDE 132                       // 128 + 4 pad: conflict-free gather stores
#define SMEM_FLOATS (128 * AS_STRIDE + 32 * 128)
#define SMEM_BYTES (SMEM_FLOATS * 4)        // 83968

__device__ float g_u[(size_t)N_NODES * HID];
__device__ float g_v[(size_t)N_NODES * HID];

// ---------------- f32x2 packed-math helpers ----------------
__device__ __forceinline__ unsigned long long pack2(float lo, float hi) {
    unsigned long long r;
    asm("mov.b64 %0, {%1, %2};" : "=l"(r) : "f"(lo), "f"(hi));
    return r;
}
__device__ __forceinline__ void unpack2(unsigned long long p, float& lo, float& hi) {
    asm("mov.b64 {%0, %1}, %2;" : "=f"(lo), "=f"(hi) : "l"(p));
}
__device__ __forceinline__ unsigned long long ffma2(unsigned long long a,
                                                    unsigned long long b,
                                                    unsigned long long c) {
    unsigned long long d;
    asm("fma.rn.f32x2 %0, %1, %2, %3;" : "=l"(d) : "l"(a), "l"(b), "l"(c));
    return d;
}
__device__ __forceinline__ float eluf(float v) {
    return v > 0.0f ? v : (__expf(v) - 1.0f);
}

// ---------------- 128x128x128 GEMM tile ----------------
// acc[8][4] (f32x2 pairs over N) += As[128][K=128] @ Bg[128][128]
// As: smem row-major, stride AS_STRIDE. Ws: smem staging 32x128 (one kt block).
// Thread (r=tid>>4, c=tid&15): rows m0=r*8..+7, cols n0=c*8..+7.
__device__ __forceinline__ void gemm128(const float* __restrict__ As,
                                        const float* __restrict__ Bg,
                                        float* Ws, int tid, int m0, int n0,
                                        unsigned long long acc[8][4]) {
#pragma unroll 1
    for (int kt = 0; kt < 128; kt += 32) {
        // stage B kt-block: 32x128 floats = 1024 float4, 4 per thread
        float4 v[4];
#pragma unroll
        for (int it = 0; it < 4; ++it) {
            int f4 = tid + 256 * it;
            v[it] = *(const float4*)(Bg + (size_t)(kt + (f4 >> 5)) * 128 +
                                     ((f4 & 31) << 2));
        }
        __syncthreads();   // prior kt's Ws reads complete (kt=0: covers As writes)
#pragma unroll
        for (int it = 0; it < 4; ++it) {
            int f4 = tid + 256 * it;
            *(float4*)(Ws + (f4 >> 5) * 128 + ((f4 & 31) << 2)) = v[it];
        }
        __syncthreads();

#pragma unroll
        for (int kk4 = 0; kk4 < 32; kk4 += 4) {
            float4 Af[8];
#pragma unroll
            for (int i = 0; i < 8; ++i)
                Af[i] = *(const float4*)(As + (m0 + i) * AS_STRIDE + kt + kk4);
#pragma unroll
            for (int t = 0; t < 4; ++t) {
                const ulonglong2* bp =
                    (const ulonglong2*)(Ws + (kk4 + t) * 128 + n0);
                ulonglong2 b01 = bp[0];
                ulonglong2 b23 = bp[1];
#pragma unroll
                for (int i = 0; i < 8; ++i) {
                    float a = (t == 0) ? Af[i].x
                            : (t == 1) ? Af[i].y
                            : (t == 2) ? Af[i].z : Af[i].w;
                    unsigned long long ap = pack2(a, a);
                    acc[i][0] = ffma2(ap, b01.x, acc[i][0]);
                    acc[i][1] = ffma2(ap, b01.y, acc[i][1]);
                    acc[i][2] = ffma2(ap, b23.x, acc[i][2]);
                    acc[i][3] = ffma2(ap, b23.y, acc[i][3]);
                }
            }
        }
    }
    __syncthreads();   // allow caller to reuse Ws / exit cleanly
}

// ---------------- kernel 1: per-node precompute u, v ----------------
__global__ __launch_bounds__(256, 2) void node_precompute(
    const float* __restrict__ x, const float* __restrict__ W1) {
    extern __shared__ float sm[];
    float* As = sm;                       // 128 x 132
    float* Ws = sm + 128 * AS_STRIDE;     // 32 x 128

    int tid = threadIdx.x;
    int nbase = blockIdx.x * 128;

    // load x tile: thread handles row m=tid>>1, half h=tid&1 (64 cols)
    {
        int m = tid >> 1, h = tid & 1;
        int node = nbase + m;
        const float4* xp = (const float4*)(x + (size_t)(node < N_NODES ? node : 0) * HID + h * 64);
        float4* dst = (float4*)(As + m * AS_STRIDE + h * 64);
        bool ok = node < N_NODES;
#pragma unroll
        for (int j = 0; j < 16; ++j) {
            float4 val = make_float4(0.f, 0.f, 0.f, 0.f);
            if (ok) val = xp[j];
            dst[j] = val;
        }
    }

    int r = tid >> 4, c = tid & 15;
    int m0 = r * 8, n0 = c * 8;

#pragma unroll 1
    for (int half = 0; half < 2; ++half) {
        unsigned long long acc[8][4];
#pragma unroll
        for (int i = 0; i < 8; ++i)
#pragma unroll
            for (int j = 0; j < 4; ++j) acc[i][j] = 0ULL;

        gemm128(As, W1 + (size_t)half * 128 * 128, Ws, tid, m0, n0, acc);

        float* dst = half ? g_v : g_u;
#pragma unroll
        for (int i = 0; i < 8; ++i) {
            int node = nbase + m0 + i;
            if (node < N_NODES) {
                float o[8];
                unpack2(acc[i][0], o[0], o[1]);
                unpack2(acc[i][1], o[2], o[3]);
                unpack2(acc[i][2], o[4], o[5]);
                unpack2(acc[i][3], o[6], o[7]);
                float4* dp = (float4*)(dst + (size_t)node * HID + n0);
                dp[0] = make_float4(o[0], o[1], o[2], o[3]);
                dp[1] = make_float4(o[4], o[5], o[6], o[7]);
            }
        }
    }
}

// ---------------- kernel 2: per-edge fused MLP ----------------
__global__ __launch_bounds__(256, 2) void edge_mlp(
    const int* __restrict__ ei,           // int64 ref -> int32 on device
    const float* __restrict__ b1,
    const float* __restrict__ W2, const float* __restrict__ b2,
    const float* __restrict__ W3, const float* __restrict__ b3,
    float* __restrict__ out) {
    extern __shared__ float sm[];
    float* Hs = sm;                       // 128 x 132: elu(u[src]+v[tgt]+b1)
    float* Ws = sm + 128 * AS_STRIDE;     // 32 x 128

    int tid = threadIdx.x;
    int ebase = blockIdx.x * 128;

    // ---- gather + layer-1 epilogue ----
    {
        int m = tid >> 1, h = tid & 1;
        int e = ebase + m;
        int eidx = e < N_EDGES ? e : 0;
        int src = ei[eidx];
        int tgt = ei[N_EDGES + eidx];
        const float4* up = (const float4*)(g_u + (size_t)src * HID + h * 64);
        const float4* vp = (const float4*)(g_v + (size_t)tgt * HID + h * 64);
        const float4* bp = (const float4*)(b1 + h * 64);
        float4* hrow = (float4*)(Hs + m * AS_STRIDE + h * 64);
#pragma unroll
        for (int j = 0; j < 16; ++j) {
            float4 a = up[j];
            float4 b = vp[j];
            float4 bb = bp[j];
            float4 o;
            o.x = eluf(a.x + b.x + bb.x);
            o.y = eluf(a.y + b.y + bb.y);
            o.z = eluf(a.z + b.z + bb.z);
            o.w = eluf(a.w + b.w + bb.w);
            hrow[j] = o;
        }
    }

    // ---- layer 2: Hs @ W2 + b2 ----
    int r = tid >> 4, c = tid & 15;
    int m0 = r * 8, n0 = c * 8;

    unsigned long long acc[8][4];
    {
        ulonglong2 t0 = *(const ulonglong2*)(b2 + n0);
        ulonglong2 t1 = *(const ulonglong2*)(b2 + n0 + 4);
#pragma unroll
        for (int i = 0; i < 8; ++i) {
            acc[i][0] = t0.x; acc[i][1] = t0.y;
            acc[i][2] = t1.x; acc[i][3] = t1.y;
        }
    }

    gemm128(Hs, W2, Ws, tid, m0, n0, acc);   // first sync covers Hs writes

    // ---- layer 3: elu + dot with W3 + 16-lane reduce ----
    float4 w3a = *(const float4*)(W3 + n0);
    float4 w3b = *(const float4*)(W3 + n0 + 4);
    float bias3 = b3[0];

    float part[8];
#pragma unroll
    for (int i = 0; i < 8; ++i) {
        float o[8];
        unpack2(acc[i][0], o[0], o[1]);
        unpack2(acc[i][1], o[2], o[3]);
        unpack2(acc[i][2], o[4], o[5]);
        unpack2(acc[i][3], o[6], o[7]);
        float p;
        p  = eluf(o[0]) * w3a.x;
        p += eluf(o[1]) * w3a.y;
        p += eluf(o[2]) * w3a.z;
        p += eluf(o[3]) * w3a.w;
        p += eluf(o[4]) * w3b.x;
        p += eluf(o[5]) * w3b.y;
        p += eluf(o[6]) * w3b.z;
        p += eluf(o[7]) * w3b.w;
        part[i] = p;
    }

#pragma unroll
    for (int i = 0; i < 8; ++i) {
#pragma unroll
        for (int off = 8; off > 0; off >>= 1)
            part[i] += __shfl_xor_sync(0xffffffffu, part[i], off, 16);
    }

    if (c == 0) {
#pragma unroll
        for (int i = 0; i < 8; ++i) {
            int e = ebase + m0 + i;
            if (e < N_EDGES) out[e] = part[i] + bias3;
        }
    }
}

// ---------------- launch ----------------
extern "C" void kernel_launch(void* const* d_in, const int* in_sizes, int n_in,
                              void* d_out, int out_size) {
    const float* x  = (const float*)d_in[0];
    const int*   ei = (const int*)d_in[1];
    const float* W1 = (const float*)d_in[2];
    const float* b1 = (const float*)d_in[3];
    const float* W2 = (const float*)d_in[4];
    const float* b2 = (const float*)d_in[5];
    const float* W3 = (const float*)d_in[6];
    const float* b3 = (const float*)d_in[7];
    float* out = (float*)d_out;

    cudaFuncSetAttribute(node_precompute,
                         cudaFuncAttributeMaxDynamicSharedMemorySize, SMEM_BYTES);
    cudaFuncSetAttribute(edge_mlp,
                         cudaFuncAttributeMaxDynamicSharedMemorySize, SMEM_BYTES);

    node_precompute<<<(N_NODES + 127) / 128, 256, SMEM_BYTES>>>(x, W1);
    edge_mlp<<<(N_EDGES + 127) / 128, 256, SMEM_BYTES>>>(ei, b1, W2, b2, W3, b3, out);
}

// round 5
// speedup vs baseline: 2.1352x; 1.6588x over previous
#include <cuda_runtime.h>
#include <cstdint>

#define N_NODES 100000
#define N_EDGES 600000
#define HID 128
#define WSTRIDE 132
#define NODE_TILES ((N_NODES + 63) / 64)   // 1563
#define EDGE_TILES (N_EDGES / 64)          // 9375 (exact)

// -------- device scratch --------
__device__ float g_u[(size_t)N_NODES * HID];
__device__ float g_v[(size_t)N_NODES * HID];
// transposed [n][k] (stride WSTRIDE), tf32 split weights
__device__ float g_w1u_hi[HID * WSTRIDE];
__device__ float g_w1u_lo[HID * WSTRIDE];
__device__ float g_w1v_hi[HID * WSTRIDE];
__device__ float g_w1v_lo[HID * WSTRIDE];
__device__ float g_w2t[HID * WSTRIDE];

// -------- helpers --------
__device__ __forceinline__ float totf32(float x) {
    float o; asm("cvt.rna.tf32.f32 %0, %1;" : "=f"(o) : "f"(x)); return o;
}
__device__ __forceinline__ float eluf(float v) {
    return v > 0.0f ? v : (__expf(v) - 1.0f);
}
__device__ __forceinline__ void mma8(float d[4], const uint32_t a[4], const uint32_t b[2]) {
    asm volatile(
        "mma.sync.aligned.m16n8k8.row.col.f32.tf32.tf32.f32 "
        "{%0,%1,%2,%3}, {%4,%5,%6,%7}, {%8,%9}, {%0,%1,%2,%3};"
        : "+f"(d[0]), "+f"(d[1]), "+f"(d[2]), "+f"(d[3])
        : "r"(a[0]), "r"(a[1]), "r"(a[2]), "r"(a[3]), "r"(b[0]), "r"(b[1]));
}

// acc[2][4][4] += A(64x128, smem stride WSTRIDE) @ B^T (B stored [n][k], stride WSTRIDE)
// warp tile: rows 32*warp_m..+31, cols 32*warp_n..+31; lane: g=lane>>2, tig=lane&3
__device__ __forceinline__ void mma_pass(const float* __restrict__ As,
                                         const float* __restrict__ Bs,
                                         float acc[2][4][4],
                                         int warp_m, int warp_n, int g, int tig) {
#pragma unroll
    for (int ks = 0; ks < 16; ++ks) {
        const int k0 = ks * 8;
        uint32_t a[2][4];
#pragma unroll
        for (int mt = 0; mt < 2; ++mt) {
            const float* p0 = As + (warp_m * 32 + mt * 16 + g) * WSTRIDE + k0 + tig;
            const float* p1 = p0 + 8 * WSTRIDE;
            a[mt][0] = __float_as_uint(p0[0]);
            a[mt][1] = __float_as_uint(p1[0]);
            a[mt][2] = __float_as_uint(p0[4]);
            a[mt][3] = __float_as_uint(p1[4]);
        }
        uint32_t b[4][2];
#pragma unroll
        for (int nt = 0; nt < 4; ++nt) {
            const float* q = Bs + (warp_n * 32 + nt * 8 + g) * WSTRIDE + k0 + tig;
            b[nt][0] = __float_as_uint(q[0]);
            b[nt][1] = __float_as_uint(q[4]);
        }
#pragma unroll
        for (int mt = 0; mt < 2; ++mt)
#pragma unroll
            for (int nt = 0; nt < 4; ++nt)
                mma8(acc[mt][nt], a[mt], b[nt]);
    }
}

// ================= prep: transpose + tf32-split weights =================
__global__ void prep_weights(const float* __restrict__ W1, const float* __restrict__ W2) {
    int idx = blockIdx.x * 256 + threadIdx.x;
    if (idx >= 128 * 128) return;
    int n = idx >> 7, k = idx & 127;
    int o = n * WSTRIDE + k;
    float wu = W1[(size_t)k * 128 + n];
    float wv = W1[(size_t)(k + 128) * 128 + n];
    float uh = totf32(wu), vh = totf32(wv);
    g_w1u_hi[o] = uh; g_w1u_lo[o] = totf32(wu - uh);
    g_w1v_hi[o] = vh; g_w1v_lo[o] = totf32(wv - vh);
    g_w2t[o] = totf32(W2[(size_t)k * 128 + n]);
}

// ================= node kernel: dst = x @ Whalf (3xTF32, ~fp32 accurate) =================
#define NODE_SMEM_FLOATS (128 * WSTRIDE * 2 + 64 * WSTRIDE * 2)
#define NODE_SMEM_BYTES (NODE_SMEM_FLOATS * 4)   // 202752

__global__ __launch_bounds__(256, 1) void node_half(const float* __restrict__ x, int half) {
    extern __shared__ float sm[];
    float* Whi = sm;                        // 128 x 132
    float* Wlo = Whi + 128 * WSTRIDE;       // 128 x 132
    float* Xhi = Wlo + 128 * WSTRIDE;       // 64 x 132
    float* Xlo = Xhi + 64 * WSTRIDE;        // 64 x 132

    const float* whi = half ? g_w1v_hi : g_w1u_hi;
    const float* wlo = half ? g_w1v_lo : g_w1u_lo;
    float* dst = half ? g_v : g_u;

    int tid = threadIdx.x;
    for (int i = tid; i < 128 * WSTRIDE / 4; i += 256) {
        ((float4*)Whi)[i] = ((const float4*)whi)[i];
        ((float4*)Wlo)[i] = ((const float4*)wlo)[i];
    }

    int lane = tid & 31, wid = tid >> 5;
    int g = lane >> 2, tig = lane & 3;
    int warp_m = wid >> 2, warp_n = wid & 3;
    int row = tid >> 2, qq = tid & 3;

    for (int t = blockIdx.x; t < NODE_TILES; t += gridDim.x) {
        // stage x rows: 4 threads per row
        {
            int node = t * 64 + row;
            const float* xr = x + (size_t)(node < N_NODES ? node : 0) * HID;
#pragma unroll
            for (int j = 0; j < 8; ++j) {
                int col = j * 16 + qq * 4;
                float4 v = *(const float4*)(xr + col);
                float4 hi, lo;
                hi.x = totf32(v.x); lo.x = totf32(v.x - hi.x);
                hi.y = totf32(v.y); lo.y = totf32(v.y - hi.y);
                hi.z = totf32(v.z); lo.z = totf32(v.z - hi.z);
                hi.w = totf32(v.w); lo.w = totf32(v.w - hi.w);
                *(float4*)(Xhi + row * WSTRIDE + col) = hi;
                *(float4*)(Xlo + row * WSTRIDE + col) = lo;
            }
        }
        __syncthreads();

        float acc[2][4][4];
#pragma unroll
        for (int i = 0; i < 2; ++i)
#pragma unroll
            for (int j = 0; j < 4; ++j)
#pragma unroll
                for (int l = 0; l < 4; ++l) acc[i][j][l] = 0.0f;

        mma_pass(Xhi, Whi, acc, warp_m, warp_n, g, tig);
        mma_pass(Xlo, Whi, acc, warp_m, warp_n, g, tig);
        mma_pass(Xhi, Wlo, acc, warp_m, warp_n, g, tig);

#pragma unroll
        for (int mt = 0; mt < 2; ++mt) {
            int r0 = t * 64 + warp_m * 32 + mt * 16 + g;
#pragma unroll
            for (int nt = 0; nt < 4; ++nt) {
                int c0 = warp_n * 32 + nt * 8 + 2 * tig;
                if (r0 < N_NODES)
                    *(float2*)(dst + (size_t)r0 * HID + c0) =
                        make_float2(acc[mt][nt][0], acc[mt][nt][1]);
                if (r0 + 8 < N_NODES)
                    *(float2*)(dst + (size_t)(r0 + 8) * HID + c0) =
                        make_float2(acc[mt][nt][2], acc[mt][nt][3]);
            }
        }
        __syncthreads();
    }
}

// ================= edge kernel: gather + elu + GEMM(tf32) + elu + W3 dot =================
// smem: W2 [128][132] + H [64][132] + red[64][4] + b1,b2,w3
#define E_RED   (128 * WSTRIDE + 64 * WSTRIDE)        // 25344
#define E_B1    (E_RED + 256)                         // 25600
#define E_B2    (E_B1 + 128)
#define E_W3    (E_B2 + 128)
#define EDGE_SMEM_FLOATS (E_W3 + 128)                 // 25984
#define EDGE_SMEM_BYTES (EDGE_SMEM_FLOATS * 4)        // 103936

__global__ __launch_bounds__(256, 2) void edge_mlp(
    const int* __restrict__ ei, const float* __restrict__ b1,
    const float* __restrict__ b2, const float* __restrict__ W3,
    const float* __restrict__ b3, float* __restrict__ out) {
    extern __shared__ float sm[];
    float* W2s = sm;                        // 128 x 132
    float* Hs  = W2s + 128 * WSTRIDE;       // 64 x 132
    float* red = sm + E_RED;                // 64 x 4
    float* b1s = sm + E_B1;
    float* b2s = sm + E_B2;
    float* w3s = sm + E_W3;

    int tid = threadIdx.x;
    for (int i = tid; i < 128 * WSTRIDE / 4; i += 256)
        ((float4*)W2s)[i] = ((const float4*)g_w2t)[i];
    if (tid < 128) {
        b1s[tid] = b1[tid];
        b2s[tid] = b2[tid];
        w3s[tid] = W3[tid];
    }
    float bias3 = b3[0];

    int lane = tid & 31, wid = tid >> 5;
    int g = lane >> 2, tig = lane & 3;
    int warp_m = wid >> 2, warp_n = wid & 3;
    int row = tid >> 2, qq = tid & 3;

    for (int t = blockIdx.x; t < EDGE_TILES; t += gridDim.x) {
        __syncthreads();   // prior iter: red reads & Hs reads complete

        // ---- gather + layer-1 epilogue (u[src]+v[tgt]+b1, elu, tf32) ----
        {
            int e = t * 64 + row;              // EDGE_TILES*64 == N_EDGES exactly
            int src = ei[e];
            int tgt = ei[N_EDGES + e];
            const float* ur = g_u + (size_t)src * HID;
            const float* vr = g_v + (size_t)tgt * HID;
#pragma unroll
            for (int j = 0; j < 8; ++j) {
                int col = j * 16 + qq * 4;
                float4 a = *(const float4*)(ur + col);
                float4 b = *(const float4*)(vr + col);
                float4 bi = *(const float4*)(b1s + col);
                float4 h;
                h.x = totf32(eluf(a.x + b.x + bi.x));
                h.y = totf32(eluf(a.y + b.y + bi.y));
                h.z = totf32(eluf(a.z + b.z + bi.z));
                h.w = totf32(eluf(a.w + b.w + bi.w));
                *(float4*)(Hs + row * WSTRIDE + col) = h;
            }
        }
        __syncthreads();

        // ---- layer 2 GEMM ----
        float acc[2][4][4];
#pragma unroll
        for (int i = 0; i < 2; ++i)
#pragma unroll
            for (int j = 0; j < 4; ++j)
#pragma unroll
                for (int l = 0; l < 4; ++l) acc[i][j][l] = 0.0f;

        mma_pass(Hs, W2s, acc, warp_m, warp_n, g, tig);

        // ---- layer 3: elu(acc+b2) . W3, reduce ----
        float p[4] = {0.f, 0.f, 0.f, 0.f};
#pragma unroll
        for (int mt = 0; mt < 2; ++mt) {
#pragma unroll
            for (int nt = 0; nt < 4; ++nt) {
                int c0 = warp_n * 32 + nt * 8 + 2 * tig;
                float w0 = w3s[c0], w1 = w3s[c0 + 1];
                float bb0 = b2s[c0], bb1 = b2s[c0 + 1];
                p[mt * 2 + 0] += eluf(acc[mt][nt][0] + bb0) * w0 +
                                 eluf(acc[mt][nt][1] + bb1) * w1;
                p[mt * 2 + 1] += eluf(acc[mt][nt][2] + bb0) * w0 +
                                 eluf(acc[mt][nt][3] + bb1) * w1;
            }
        }
#pragma unroll
        for (int i = 0; i < 4; ++i) {
            p[i] += __shfl_xor_sync(0xffffffffu, p[i], 1);
            p[i] += __shfl_xor_sync(0xffffffffu, p[i], 2);
        }
        if (tig == 0) {
#pragma unroll
            for (int mt = 0; mt < 2; ++mt) {
                int rl = warp_m * 32 + mt * 16 + g;
                red[rl * 4 + warp_n] = p[mt * 2 + 0];
                red[(rl + 8) * 4 + warp_n] = p[mt * 2 + 1];
            }
        }
        __syncthreads();

        if (tid < 64)
            out[t * 64 + tid] = red[tid * 4 + 0] + red[tid * 4 + 1] +
                                red[tid * 4 + 2] + red[tid * 4 + 3] + bias3;
    }
}

// ================= launch =================
extern "C" void kernel_launch(void* const* d_in, const int* in_sizes, int n_in,
                              void* d_out, int out_size) {
    const float* x  = (const float*)d_in[0];
    const int*   ei = (const int*)d_in[1];
    const float* W1 = (const float*)d_in[2];
    const float* b1 = (const float*)d_in[3];
    const float* W2 = (const float*)d_in[4];
    const float* b2 = (const float*)d_in[5];
    const float* W3 = (const float*)d_in[6];
    const float* b3 = (const float*)d_in[7];
    float* out = (float*)d_out;

    cudaFuncSetAttribute(node_half,
                         cudaFuncAttributeMaxDynamicSharedMemorySize, NODE_SMEM_BYTES);
    cudaFuncSetAttribute(edge_mlp,
                         cudaFuncAttributeMaxDynamicSharedMemorySize, EDGE_SMEM_BYTES);

    prep_weights<<<64, 256>>>(W1, W2);
    node_half<<<148, 256, NODE_SMEM_BYTES>>>(x, 0);
    node_half<<<148, 256, NODE_SMEM_BYTES>>>(x, 1);
    edge_mlp<<<296, 256, EDGE_SMEM_BYTES>>>(ei, b1, b2, W3, b3, out);
}

// round 6
// speedup vs baseline: 3.9760x; 1.8621x over previous
#include <cuda_runtime.h>
#include <cuda_fp16.h>
#include <cstdint>

#define N_NODES 100000
#define N_EDGES 600000
#define HID 128
#define WSTRIDE 132                       // node fp32 tile stride (floats)
#define ERS 144                           // edge fp16 row stride (halves)
#define NODE_TILES ((N_NODES + 63) / 64)  // 1563
#define EDGE_TILES (N_EDGES / 64)         // 9375 exact

// -------- device scratch --------
__device__ __align__(16) __half g_u[(size_t)N_NODES * HID];
__device__ __align__(16) __half g_v[(size_t)N_NODES * HID];
__device__ __align__(16) float  g_w1u[HID * WSTRIDE];   // [n][k] tf32, node layout
__device__ __align__(16) float  g_w1v[HID * WSTRIDE];
__device__ __align__(16) __half g_w2h[HID * ERS];       // [n][perm(k)] fp16, edge layout

// -------- helpers --------
__device__ __forceinline__ float totf32(float x) {
    float o; asm("cvt.rna.tf32.f32 %0, %1;" : "=f"(o) : "f"(x)); return o;
}
__device__ __forceinline__ float eluf(float v) {
    return v > 0.0f ? v : (__expf(v) - 1.0f);
}
// k-permutation: within each 16-block, orig offsets {2t,2t+1,2t+8,2t+9} -> slots 4t+{0,1,2,3}
__host__ __device__ __forceinline__ int p16(int k) {
    int blk = k >> 4, o = k & 15;
    int t = (o & 7) >> 1;
    int pos = (o < 8) ? (4 * t + (o & 1)) : (4 * t + 2 + (o & 1));
    return blk * 16 + pos;
}

// tf32 m16n8k8 (node)
__device__ __forceinline__ void mma8(float d[4], const uint32_t a[4], const uint32_t b[2]) {
    asm volatile(
        "mma.sync.aligned.m16n8k8.row.col.f32.tf32.tf32.f32 "
        "{%0,%1,%2,%3}, {%4,%5,%6,%7}, {%8,%9}, {%0,%1,%2,%3};"
        : "+f"(d[0]), "+f"(d[1]), "+f"(d[2]), "+f"(d[3])
        : "r"(a[0]), "r"(a[1]), "r"(a[2]), "r"(a[3]), "r"(b[0]), "r"(b[1]));
}
// fp16 m16n8k16 f32-accum (edge)
__device__ __forceinline__ void mma16(float d[4], uint32_t a0, uint32_t a1, uint32_t a2,
                                      uint32_t a3, uint32_t b0, uint32_t b1) {
    asm volatile(
        "mma.sync.aligned.m16n8k16.row.col.f32.f16.f16.f32 "
        "{%0,%1,%2,%3}, {%4,%5,%6,%7}, {%8,%9}, {%0,%1,%2,%3};"
        : "+f"(d[0]), "+f"(d[1]), "+f"(d[2]), "+f"(d[3])
        : "r"(a0), "r"(a1), "r"(a2), "r"(a3), "r"(b0), "r"(b1));
}

// ================= prep =================
__global__ void prep_weights(const float* __restrict__ W1, const float* __restrict__ W2) {
    int idx = blockIdx.x * 256 + threadIdx.x;
    if (idx >= 128 * 128) return;
    int n = idx >> 7, k = idx & 127;
    g_w1u[n * WSTRIDE + k] = totf32(W1[(size_t)k * 128 + n]);
    g_w1v[n * WSTRIDE + k] = totf32(W1[(size_t)(k + 128) * 128 + n]);
    g_w2h[n * ERS + p16(k)] = __float2half(W2[(size_t)k * 128 + n]);
}

// ================= node: u,v = x @ W1 halves (single-pass tf32, fp16 out) =================
#define NODE_SMEM_BYTES ((128 * WSTRIDE + 64 * WSTRIDE) * 4)   // 101376

__global__ __launch_bounds__(256, 2) void node_precompute(const float* __restrict__ x) {
    extern __shared__ float sm[];
    float* Ws = sm;                        // 128 x 132 (one W1 half)
    float* Xs = Ws + 128 * WSTRIDE;        // 64 x 132

    int half = blockIdx.x & 1;
    const float* wsrc = half ? g_w1v : g_w1u;
    __half* dst = half ? g_v : g_u;

    int tid = threadIdx.x;
    for (int i = tid; i < 128 * WSTRIDE / 4; i += 256)
        ((float4*)Ws)[i] = ((const float4*)wsrc)[i];

    int lane = tid & 31, wid = tid >> 5;
    int g = lane >> 2, tg = lane & 3;
    int wm = wid >> 2, wn = wid & 3;
    int row = tid >> 2, qq = tid & 3;

    for (int t = blockIdx.x >> 1; t < NODE_TILES; t += gridDim.x >> 1) {
        // stage x tile (tf32)
        {
            int node = t * 64 + row;
            const float* xr = x + (size_t)(node < N_NODES ? node : 0) * HID;
#pragma unroll
            for (int j = 0; j < 8; ++j) {
                int col = j * 16 + qq * 4;
                float4 v = *(const float4*)(xr + col);
                v.x = totf32(v.x); v.y = totf32(v.y);
                v.z = totf32(v.z); v.w = totf32(v.w);
                *(float4*)(Xs + row * WSTRIDE + col) = v;
            }
        }
        __syncthreads();

        float acc[2][4][4];
#pragma unroll
        for (int i = 0; i < 2; ++i)
#pragma unroll
            for (int j = 0; j < 4; ++j)
#pragma unroll
                for (int l = 0; l < 4; ++l) acc[i][j][l] = 0.0f;

#pragma unroll
        for (int ks = 0; ks < 16; ++ks) {
            const int k0 = ks * 8;
            uint32_t a[2][4];
#pragma unroll
            for (int mt = 0; mt < 2; ++mt) {
                const float* p0 = Xs + (wm * 32 + mt * 16 + g) * WSTRIDE + k0 + tg;
                const float* p1 = p0 + 8 * WSTRIDE;
                a[mt][0] = __float_as_uint(p0[0]);
                a[mt][1] = __float_as_uint(p1[0]);
                a[mt][2] = __float_as_uint(p0[4]);
                a[mt][3] = __float_as_uint(p1[4]);
            }
            uint32_t b[4][2];
#pragma unroll
            for (int nt = 0; nt < 4; ++nt) {
                const float* q = Ws + (wn * 32 + nt * 8 + g) * WSTRIDE + k0 + tg;
                b[nt][0] = __float_as_uint(q[0]);
                b[nt][1] = __float_as_uint(q[4]);
            }
#pragma unroll
            for (int mt = 0; mt < 2; ++mt)
#pragma unroll
                for (int nt = 0; nt < 4; ++nt)
                    mma8(acc[mt][nt], a[mt], b[nt]);
        }

#pragma unroll
        for (int mt = 0; mt < 2; ++mt) {
            int r0 = t * 64 + wm * 32 + mt * 16 + g;
#pragma unroll
            for (int nt = 0; nt < 4; ++nt) {
                int c0 = wn * 32 + nt * 8 + 2 * tg;
                if (r0 < N_NODES)
                    *(__half2*)(dst + (size_t)r0 * HID + c0) =
                        __floats2half2_rn(acc[mt][nt][0], acc[mt][nt][1]);
                if (r0 + 8 < N_NODES)
                    *(__half2*)(dst + (size_t)(r0 + 8) * HID + c0) =
                        __floats2half2_rn(acc[mt][nt][2], acc[mt][nt][3]);
            }
        }
        __syncthreads();
    }
}

// ================= edge: gather + elu -> fp16 GEMM -> elu + W3 dot =================
// smem bytes: W2s 36864 | Hs 18432 | b1 512 | b2 512 | w3 512 | red 1024 = 57856
#define W2S_OFF 0
#define HS_OFF  36864
#define B1_OFF  55296
#define B2_OFF  55808
#define W3_OFF  56320
#define RED_OFF 56832
#define EDGE_SMEM_BYTES 57856

__global__ __launch_bounds__(256, 3) void edge_mlp(
    const int* __restrict__ ei, const float* __restrict__ b1,
    const float* __restrict__ b2, const float* __restrict__ W3,
    const float* __restrict__ b3, float* __restrict__ out) {
    extern __shared__ char smc[];
    __half* W2s = (__half*)(smc + W2S_OFF);   // 128 x 144
    __half* Hs  = (__half*)(smc + HS_OFF);    // 64 x 144
    float* b1s = (float*)(smc + B1_OFF);
    float* b2s = (float*)(smc + B2_OFF);
    float* w3s = (float*)(smc + W3_OFF);
    float* red = (float*)(smc + RED_OFF);     // 64 x 4

    int tid = threadIdx.x;
    // 128*144 halves = 2304 uint4
    for (int i = tid; i < 2304; i += 256)
        ((uint4*)W2s)[i] = ((const uint4*)g_w2h)[i];
    if (tid < 128) {
        b1s[tid] = b1[tid];
        b2s[tid] = b2[tid];
        w3s[tid] = W3[tid];
    }
    float bias3 = b3[0];
    __syncthreads();

    int lane = tid & 31, wid = tid >> 5;
    int g = lane >> 2, tg = lane & 3;
    int wm = wid >> 2, wn = wid & 3;
    int row = tid >> 2, qq = tid & 3;

    for (int t = blockIdx.x; t < EDGE_TILES; t += gridDim.x) {
        // ---- gather (fp16 u,v) + layer-1 epilogue into permuted Hs ----
        {
            int e = t * 64 + row;
            int src = ei[e];
            int tgt = ei[N_EDGES + e];
            const uint4* up = ((const uint4*)(g_u + (size_t)src * HID)) + 4 * qq;
            const uint4* vp = ((const uint4*)(g_v + (size_t)tgt * HID)) + 4 * qq;
            uint4 U[4], V[4];
#pragma unroll
            for (int i = 0; i < 4; ++i) { U[i] = up[i]; V[i] = vp[i]; }
            const __half2* uh = (const __half2*)U;
            const __half2* vh = (const __half2*)V;
#pragma unroll
            for (int blk = 0; blk < 2; ++blk) {
                uint32_t h[8];
#pragma unroll
                for (int i = 0; i < 8; ++i) {
                    float2 uf = __half22float2(uh[blk * 8 + i]);
                    float2 vf = __half22float2(vh[blk * 8 + i]);
                    int c = qq * 32 + blk * 16 + 2 * i;
                    float2 bb = *(const float2*)(b1s + c);
                    __half2 hv = __floats2half2_rn(eluf(uf.x + vf.x + bb.x),
                                                   eluf(uf.y + vf.y + bb.y));
                    h[i] = *(uint32_t*)&hv;
                }
                uint4* dst = (uint4*)(Hs + row * ERS + (2 * qq + blk) * 16);
                dst[0] = make_uint4(h[0], h[4], h[1], h[5]);
                dst[1] = make_uint4(h[2], h[6], h[3], h[7]);
            }
        }
        __syncthreads();

        // ---- layer 2: fp16 MMA ----
        float acc[2][4][4];
#pragma unroll
        for (int i = 0; i < 2; ++i)
#pragma unroll
            for (int j = 0; j < 4; ++j)
#pragma unroll
                for (int l = 0; l < 4; ++l) acc[i][j][l] = 0.0f;

        int m0 = wm * 32, n0 = wn * 32;
#pragma unroll
        for (int ks = 0; ks < 8; ++ks) {
            int sc = ks * 16 + tg * 4;   // permuted fp16 column
            uint2 a0[2], a1[2];
#pragma unroll
            for (int mt = 0; mt < 2; ++mt) {
                a0[mt] = *(const uint2*)(Hs + (m0 + mt * 16 + g) * ERS + sc);
                a1[mt] = *(const uint2*)(Hs + (m0 + mt * 16 + 8 + g) * ERS + sc);
            }
            uint2 bq[4];
#pragma unroll
            for (int nt = 0; nt < 4; ++nt)
                bq[nt] = *(const uint2*)(W2s + (n0 + nt * 8 + g) * ERS + sc);
#pragma unroll
            for (int mt = 0; mt < 2; ++mt)
#pragma unroll
                for (int nt = 0; nt < 4; ++nt)
                    mma16(acc[mt][nt], a0[mt].x, a1[mt].x, a0[mt].y, a1[mt].y,
                          bq[nt].x, bq[nt].y);
        }

        // ---- layer 3: elu(acc + b2) . W3, reduce ----
        float p0[2] = {0.f, 0.f}, p1[2] = {0.f, 0.f};
#pragma unroll
        for (int mt = 0; mt < 2; ++mt) {
#pragma unroll
            for (int nt = 0; nt < 4; ++nt) {
                int c0 = n0 + nt * 8 + 2 * tg;
                float w0 = w3s[c0], w1 = w3s[c0 + 1];
                float bb0 = b2s[c0], bb1 = b2s[c0 + 1];
                p0[mt] += eluf(acc[mt][nt][0] + bb0) * w0 +
                          eluf(acc[mt][nt][1] + bb1) * w1;
                p1[mt] += eluf(acc[mt][nt][2] + bb0) * w0 +
                          eluf(acc[mt][nt][3] + bb1) * w1;
            }
        }
#pragma unroll
        for (int mt = 0; mt < 2; ++mt) {
            p0[mt] += __shfl_xor_sync(0xffffffffu, p0[mt], 1);
            p0[mt] += __shfl_xor_sync(0xffffffffu, p0[mt], 2);
            p1[mt] += __shfl_xor_sync(0xffffffffu, p1[mt], 1);
            p1[mt] += __shfl_xor_sync(0xffffffffu, p1[mt], 2);
        }
        if (tg == 0) {
#pragma unroll
            for (int mt = 0; mt < 2; ++mt) {
                int rl = wm * 32 + mt * 16 + g;
                red[rl * 4 + wn] = p0[mt];
                red[(rl + 8) * 4 + wn] = p1[mt];
            }
        }
        __syncthreads();

        if (tid < 64)
            out[t * 64 + tid] = red[tid * 4 + 0] + red[tid * 4 + 1] +
                                red[tid * 4 + 2] + red[tid * 4 + 3] + bias3;
        // next iteration's post-gather __syncthreads orders Hs overwrite vs frag reads;
        // red overwrite happens after that barrier, out-read happens before it. Safe.
    }
}

// ================= launch =================
extern "C" void kernel_launch(void* const* d_in, const int* in_sizes, int n_in,
                              void* d_out, int out_size) {
    const float* x  = (const float*)d_in[0];
    const int*   ei = (const int*)d_in[1];
    const float* W1 = (const float*)d_in[2];
    const float* b1 = (const float*)d_in[3];
    const float* W2 = (const float*)d_in[4];
    const float* b2 = (const float*)d_in[5];
    const float* W3 = (const float*)d_in[6];
    const float* b3 = (const float*)d_in[7];
    float* out = (float*)d_out;

    cudaFuncSetAttribute(node_precompute,
                         cudaFuncAttributeMaxDynamicSharedMemorySize, NODE_SMEM_BYTES);
    cudaFuncSetAttribute(edge_mlp,
                         cudaFuncAttributeMaxDynamicSharedMemorySize, EDGE_SMEM_BYTES);

    prep_weights<<<64, 256>>>(W1, W2);
    node_precompute<<<296, 256, NODE_SMEM_BYTES>>>(x);
    edge_mlp<<<444, 256, EDGE_SMEM_BYTES>>>(ei, b1, b2, W3, b3, out);
}

// round 10
// speedup vs baseline: 4.3243x; 1.0876x over previous
#include <cuda_runtime.h>
#include <cuda_fp16.h>
#include <cstdint>

#define N_NODES 100000
#define N_EDGES 600000
#define HID 128
#define WSTRIDE 132                       // node fp32 tile stride (floats)
#define ERS 144                           // edge fp16 row stride (halves)
#define NODE_TILES ((N_NODES + 63) / 64)  // 1563
#define EDGE_TILES (N_EDGES / 64)         // 9375 exact

// -------- device scratch --------
__device__ __align__(16) __half g_u[(size_t)N_NODES * HID];   // holds u + b1 (b1 folded)
__device__ __align__(16) __half g_v[(size_t)N_NODES * HID];
__device__ __align__(16) float  g_w1u[HID * WSTRIDE];
__device__ __align__(16) float  g_w1v[HID * WSTRIDE];
__device__ __align__(16) __half g_w2h[HID * ERS];             // [n][perm(k)] fp16

// -------- helpers --------
__device__ __forceinline__ float totf32(float x) {
    float o; asm("cvt.rna.tf32.f32 %0, %1;" : "=f"(o) : "f"(x)); return o;
}
__device__ __forceinline__ float eluf(float v) {
    return v > 0.0f ? v : (__expf(v) - 1.0f);
}
__host__ __device__ __forceinline__ int p16(int k) {
    int blk = k >> 4, o = k & 15;
    int t = (o & 7) >> 1;
    int pos = (o < 8) ? (4 * t + (o & 1)) : (4 * t + 2 + (o & 1));
    return blk * 16 + pos;
}
__device__ __forceinline__ void mma8(float d[4], const uint32_t a[4], const uint32_t b[2]) {
    asm volatile(
        "mma.sync.aligned.m16n8k8.row.col.f32.tf32.tf32.f32 "
        "{%0,%1,%2,%3}, {%4,%5,%6,%7}, {%8,%9}, {%0,%1,%2,%3};"
        : "+f"(d[0]), "+f"(d[1]), "+f"(d[2]), "+f"(d[3])
        : "r"(a[0]), "r"(a[1]), "r"(a[2]), "r"(a[3]), "r"(b[0]), "r"(b[1]));
}
__device__ __forceinline__ void mma16(float d[4], uint32_t a0, uint32_t a1, uint32_t a2,
                                      uint32_t a3, uint32_t b0, uint32_t b1) {
    asm volatile(
        "mma.sync.aligned.m16n8k16.row.col.f32.f16.f16.f32 "
        "{%0,%1,%2,%3}, {%4,%5,%6,%7}, {%8,%9}, {%0,%1,%2,%3};"
        : "+f"(d[0]), "+f"(d[1]), "+f"(d[2]), "+f"(d[3])
        : "r"(a0), "r"(a1), "r"(a2), "r"(a3), "r"(b0), "r"(b1));
}

// ================= prep =================
__global__ void prep_weights(const float* __restrict__ W1, const float* __restrict__ W2) {
    int idx = blockIdx.x * 256 + threadIdx.x;
    if (idx >= 128 * 128) return;
    int n = idx >> 7, k = idx & 127;
    g_w1u[n * WSTRIDE + k] = totf32(W1[(size_t)k * 128 + n]);
    g_w1v[n * WSTRIDE + k] = totf32(W1[(size_t)(k + 128) * 128 + n]);
    g_w2h[n * ERS + p16(k)] = __float2half(W2[(size_t)k * 128 + n]);
}

// ================= node: u = x@W1u + b1 (folded), v = x@W1v ; fp16 out ========
#define NODE_SMEM_BYTES ((128 * WSTRIDE + 64 * WSTRIDE) * 4)   // 101376

__global__ __launch_bounds__(256, 2) void node_precompute(const float* __restrict__ x,
                                                          const float* __restrict__ b1) {
    extern __shared__ float sm[];
    float* Ws = sm;
    float* Xs = Ws + 128 * WSTRIDE;

    int half = blockIdx.x & 1;
    const float* wsrc = half ? g_w1v : g_w1u;
    __half* dst = half ? g_v : g_u;

    int tid = threadIdx.x;
    for (int i = tid; i < 128 * WSTRIDE / 4; i += 256)
        ((float4*)Ws)[i] = ((const float4*)wsrc)[i];

    int lane = tid & 31, wid = tid >> 5;
    int g = lane >> 2, tg = lane & 3;
    int wm = wid >> 2, wn = wid & 3;
    int row = tid >> 2, qq = tid & 3;

    // bias regs (only the u half folds b1)
    float2 bb[4];
#pragma unroll
    for (int nt = 0; nt < 4; ++nt) {
        int c0 = wn * 32 + nt * 8 + 2 * tg;
        bb[nt] = half ? make_float2(0.f, 0.f) : *(const float2*)(b1 + c0);
    }

    for (int t = blockIdx.x >> 1; t < NODE_TILES; t += gridDim.x >> 1) {
        {
            int node = t * 64 + row;
            const float* xr = x + (size_t)(node < N_NODES ? node : 0) * HID;
#pragma unroll
            for (int j = 0; j < 8; ++j) {
                int col = j * 16 + qq * 4;
                float4 v = *(const float4*)(xr + col);
                v.x = totf32(v.x); v.y = totf32(v.y);
                v.z = totf32(v.z); v.w = totf32(v.w);
                *(float4*)(Xs + row * WSTRIDE + col) = v;
            }
        }
        __syncthreads();

        float acc[2][4][4];
#pragma unroll
        for (int i = 0; i < 2; ++i)
#pragma unroll
            for (int j = 0; j < 4; ++j)
#pragma unroll
                for (int l = 0; l < 4; ++l) acc[i][j][l] = 0.0f;

#pragma unroll
        for (int ks = 0; ks < 16; ++ks) {
            const int k0 = ks * 8;
            uint32_t a[2][4];
#pragma unroll
            for (int mt = 0; mt < 2; ++mt) {
                const float* p0 = Xs + (wm * 32 + mt * 16 + g) * WSTRIDE + k0 + tg;
                const float* p1 = p0 + 8 * WSTRIDE;
                a[mt][0] = __float_as_uint(p0[0]);
                a[mt][1] = __float_as_uint(p1[0]);
                a[mt][2] = __float_as_uint(p0[4]);
                a[mt][3] = __float_as_uint(p1[4]);
            }
            uint32_t b[4][2];
#pragma unroll
            for (int nt = 0; nt < 4; ++nt) {
                const float* q = Ws + (wn * 32 + nt * 8 + g) * WSTRIDE + k0 + tg;
                b[nt][0] = __float_as_uint(q[0]);
                b[nt][1] = __float_as_uint(q[4]);
            }
#pragma unroll
            for (int mt = 0; mt < 2; ++mt)
#pragma unroll
                for (int nt = 0; nt < 4; ++nt)
                    mma8(acc[mt][nt], a[mt], b[nt]);
        }

#pragma unroll
        for (int mt = 0; mt < 2; ++mt) {
            int r0 = t * 64 + wm * 32 + mt * 16 + g;
#pragma unroll
            for (int nt = 0; nt < 4; ++nt) {
                int c0 = wn * 32 + nt * 8 + 2 * tg;
                if (r0 < N_NODES)
                    *(__half2*)(dst + (size_t)r0 * HID + c0) =
                        __floats2half2_rn(acc[mt][nt][0] + bb[nt].x,
                                          acc[mt][nt][1] + bb[nt].y);
                if (r0 + 8 < N_NODES)
                    *(__half2*)(dst + (size_t)(r0 + 8) * HID + c0) =
                        __floats2half2_rn(acc[mt][nt][2] + bb[nt].x,
                                          acc[mt][nt][3] + bb[nt].y);
            }
        }
        __syncthreads();
    }
}

// ================= edge: pipelined gather -> fp16 GEMM -> elu + W3 dot =========
// smem: W2s 36864 | H0 18432 | H1 18432 | red 2x1024 = 75776 bytes
#define W2S_OFF 0
#define H0_OFF  36864
#define H1_OFF  55296
#define RED_OFF 73728
#define EDGE_SMEM_BYTES 75776

__global__ __launch_bounds__(256, 2) void edge_mlp(
    const int* __restrict__ ei, const float* __restrict__ b2,
    const float* __restrict__ W3, const float* __restrict__ b3,
    float* __restrict__ out) {
    extern __shared__ char smc[];
    __half* W2s = (__half*)(smc + W2S_OFF);
    __half* Hb[2] = {(__half*)(smc + H0_OFF), (__half*)(smc + H1_OFF)};
    float* redb = (float*)(smc + RED_OFF);   // 2 x 64 x 4

    int tid = threadIdx.x;
    for (int i = tid; i < 2304; i += 256)
        ((uint4*)W2s)[i] = ((const uint4*)g_w2h)[i];

    int lane = tid & 31, wid = tid >> 5;
    int g = lane >> 2, tg = lane & 3;
    int wm = wid >> 2, wn = wid & 3;
    int row = tid >> 2, qq = tid & 3;
    int m0 = wm * 32, n0 = wn * 32;

    // epilogue constants in registers
    float b2r[8], w3r[8];
#pragma unroll
    for (int nt = 0; nt < 4; ++nt) {
        int c0 = n0 + nt * 8 + 2 * tg;
        b2r[2 * nt] = b2[c0];     b2r[2 * nt + 1] = b2[c0 + 1];
        w3r[2 * nt] = W3[c0];     w3r[2 * nt + 1] = W3[c0 + 1];
    }
    float bias3 = b3[0];

    // ---- prologue: gather tile blockIdx.x into H[0] ----
    {
        int e = blockIdx.x * 64 + row;
        int src = ei[e];
        int tgt = ei[N_EDGES + e];
        const uint4* up = ((const uint4*)(g_u + (size_t)src * HID)) + 4 * qq;
        const uint4* vp = ((const uint4*)(g_v + (size_t)tgt * HID)) + 4 * qq;
        uint4 U[4], V[4];
#pragma unroll
        for (int i = 0; i < 4; ++i) { U[i] = up[i]; V[i] = vp[i]; }
        const __half2* uh = (const __half2*)U;
        const __half2* vh = (const __half2*)V;
#pragma unroll
        for (int blk = 0; blk < 2; ++blk) {
            uint32_t h[8];
#pragma unroll
            for (int i = 0; i < 8; ++i) {
                float2 uf = __half22float2(uh[blk * 8 + i]);
                float2 vf = __half22float2(vh[blk * 8 + i]);
                __half2 hv = __floats2half2_rn(eluf(uf.x + vf.x), eluf(uf.y + vf.y));
                h[i] = *(uint32_t*)&hv;
            }
            uint4* dst = (uint4*)(Hb[0] + row * ERS + (2 * qq + blk) * 16);
            dst[0] = make_uint4(h[0], h[4], h[1], h[5]);
            dst[1] = make_uint4(h[2], h[6], h[3], h[7]);
        }
    }
    __syncthreads();   // covers W2s + H[0]

    int it = 0;
    int t = blockIdx.x;
    for (; t < EDGE_TILES; t += gridDim.x, ++it) {
        int cur = it & 1;
        const __half* Hc = Hb[cur];
        __half* Hn = Hb[cur ^ 1];
        float* redc = redb + cur * 256;
        const float* redp = redb + (cur ^ 1) * 256;

        // 1. output for tile t - gridDim (red from previous iter, synced)
        if (it > 0 && tid < 64)
            out[(t - (int)gridDim.x) * 64 + tid] =
                redp[tid * 4 + 0] + redp[tid * 4 + 1] +
                redp[tid * 4 + 2] + redp[tid * 4 + 3] + bias3;

        // 2. issue gather loads for next tile (non-blocking w.r.t. MMA below)
        int tn = t + gridDim.x;
        bool hn = tn < EDGE_TILES;
        uint4 U[4], V[4];
        if (hn) {
            int e = tn * 64 + row;
            int src = ei[e];
            int tgt = ei[N_EDGES + e];
            const uint4* up = ((const uint4*)(g_u + (size_t)src * HID)) + 4 * qq;
            const uint4* vp = ((const uint4*)(g_v + (size_t)tgt * HID)) + 4 * qq;
#pragma unroll
            for (int i = 0; i < 4; ++i) { U[i] = up[i]; V[i] = vp[i]; }
        }

        // 3. layer-2 MMA on H[cur]
        float acc[2][4][4];
#pragma unroll
        for (int i = 0; i < 2; ++i)
#pragma unroll
            for (int j = 0; j < 4; ++j)
#pragma unroll
                for (int l = 0; l < 4; ++l) acc[i][j][l] = 0.0f;

#pragma unroll
        for (int ks = 0; ks < 8; ++ks) {
            int sc = ks * 16 + tg * 4;
            uint2 a0[2], a1[2];
#pragma unroll
            for (int mt = 0; mt < 2; ++mt) {
                a0[mt] = *(const uint2*)(Hc + (m0 + mt * 16 + g) * ERS + sc);
                a1[mt] = *(const uint2*)(Hc + (m0 + mt * 16 + 8 + g) * ERS + sc);
            }
            uint2 bq[4];
#pragma unroll
            for (int nt = 0; nt < 4; ++nt)
                bq[nt] = *(const uint2*)(W2s + (n0 + nt * 8 + g) * ERS + sc);
#pragma unroll
            for (int mt = 0; mt < 2; ++mt)
#pragma unroll
                for (int nt = 0; nt < 4; ++nt)
                    mma16(acc[mt][nt], a0[mt].x, a1[mt].x, a0[mt].y, a1[mt].y,
                          bq[nt].x, bq[nt].y);
        }

        // 4. convert + store next H tile (consumes gather regs; overlapped by MMA)
        if (hn) {
            const __half2* uh = (const __half2*)U;
            const __half2* vh = (const __half2*)V;
#pragma unroll
            for (int blk = 0; blk < 2; ++blk) {
                uint32_t h[8];
#pragma unroll
                for (int i = 0; i < 8; ++i) {
                    float2 uf = __half22float2(uh[blk * 8 + i]);
                    float2 vf = __half22float2(vh[blk * 8 + i]);
                    __half2 hv = __floats2half2_rn(eluf(uf.x + vf.x), eluf(uf.y + vf.y));
                    h[i] = *(uint32_t*)&hv;
                }
                uint4* dst = (uint4*)(Hn + row * ERS + (2 * qq + blk) * 16);
                dst[0] = make_uint4(h[0], h[4], h[1], h[5]);
                dst[1] = make_uint4(h[2], h[6], h[3], h[7]);
            }
        }

        // 5. layer-3 epilogue -> red[cur]
        float p0[2] = {0.f, 0.f}, p1[2] = {0.f, 0.f};
#pragma unroll
        for (int mt = 0; mt < 2; ++mt) {
#pragma unroll
            for (int nt = 0; nt < 4; ++nt) {
                p0[mt] += eluf(acc[mt][nt][0] + b2r[2 * nt]) * w3r[2 * nt] +
                          eluf(acc[mt][nt][1] + b2r[2 * nt + 1]) * w3r[2 * nt + 1];
                p1[mt] += eluf(acc[mt][nt][2] + b2r[2 * nt]) * w3r[2 * nt] +
                          eluf(acc[mt][nt][3] + b2r[2 * nt + 1]) * w3r[2 * nt + 1];
            }
        }
#pragma unroll
        for (int mt = 0; mt < 2; ++mt) {
            p0[mt] += __shfl_xor_sync(0xffffffffu, p0[mt], 1);
            p0[mt] += __shfl_xor_sync(0xffffffffu, p0[mt], 2);
            p1[mt] += __shfl_xor_sync(0xffffffffu, p1[mt], 1);
            p1[mt] += __shfl_xor_sync(0xffffffffu, p1[mt], 2);
        }
        if (tg == 0) {
#pragma unroll
            for (int mt = 0; mt < 2; ++mt) {
                int rl = m0 + mt * 16 + g;
                redc[rl * 4 + wn] = p0[mt];
                redc[(rl + 8) * 4 + wn] = p1[mt];
            }
        }
        __syncthreads();
    }

    // drain: output for the final tile
    {
        const float* redp = redb + ((it - 1) & 1) * 256;
        if (tid < 64)
            out[(t - (int)gridDim.x) * 64 + tid] =
                redp[tid * 4 + 0] + redp[tid * 4 + 1] +
                redp[tid * 4 + 2] + redp[tid * 4 + 3] + bias3;
    }
}

// ================= launch =================
extern "C" void kernel_launch(void* const* d_in, const int* in_sizes, int n_in,
                              void* d_out, int out_size) {
    const float* x  = (const float*)d_in[0];
    const int*   ei = (const int*)d_in[1];
    const float* W1 = (const float*)d_in[2];
    const float* b1 = (const float*)d_in[3];
    const float* W2 = (const float*)d_in[4];
    const float* b2 = (const float*)d_in[5];
    const float* W3 = (const float*)d_in[6];
    const float* b3 = (const float*)d_in[7];
    float* out = (float*)d_out;

    cudaFuncSetAttribute(node_precompute,
                         cudaFuncAttributeMaxDynamicSharedMemorySize, NODE_SMEM_BYTES);
    cudaFuncSetAttribute(edge_mlp,
                         cudaFuncAttributeMaxDynamicSharedMemorySize, EDGE_SMEM_BYTES);

    prep_weights<<<64, 256>>>(W1, W2);
    node_precompute<<<296, 256, NODE_SMEM_BYTES>>>(x, b1);
    edge_mlp<<<296, 256, EDGE_SMEM_BYTES>>>(ei, b2, W3, b3, out);
}